// round 4
// baseline (speedup 1.0000x reference)
#include <cuda_runtime.h>

#define NBITS     20
#define NSTATES   (1u << NBITS)     // 2^20
#define QUARTER_N 262144.0f         // N/4
#define HALF_N    524288.0f         // N/2

// Single-block kernel. The buggy diag-gate cascade collapses the state to
// exactly zero at the 3rd Hadamard (fp32-exact: v0' = c*s, v1' = -c*s are
// exact negatives, so the next cross-qubit sum (N/4)(v0+v1) == 0). Hence
// probs == 0 and out = relu(b1)@W2 + b2. The W1 fallback is kept for
// mathematical faithfulness but never executes (rel_err==0 across rounds
// confirms the collapse).
//
// Perf structure: all DRAM traffic (W2 -> SMEM via float4, b1, b2) is issued
// up front with full MLP, overlapping thread 0's scalar cascade; the matvec
// epilogue runs out of SMEM with a 4-way split-K (32-long FMA chains instead
// of 128-long).
__global__ void qecm_kernel(const float* __restrict__ theta,  // [20,4]
                            const float* __restrict__ W1,     // [2^20,128]
                            const float* __restrict__ b1,     // [128]
                            const float* __restrict__ W2,     // [128,20]
                            const float* __restrict__ b2,     // [20]
                            float* __restrict__ out) {        // [1,20]
    __shared__ float    sh_W2[128 * NBITS];       // 10 KB
    __shared__ float    h[128];
    __shared__ float    part[4 * NBITS];          // split-K partials
    __shared__ float    sh_p0, sh_p1;
    __shared__ unsigned sh_mask;
    __shared__ int      sh_fast;
    const int tid = threadIdx.x;

    // ---- issue all global loads first (one DRAM round-trip, high MLP) ----
    const float4* W2v = (const float4*)W2;        // 2560 floats = 640 float4
    float4 w2r[5];
    #pragma unroll
    for (int i = 0; i < 5; i++) w2r[i] = W2v[tid + 128 * i];
    float b1v = b1[tid];
    float b2v = (tid < NBITS) ? b2[tid] : 0.0f;

    // ---- thread 0: scalar replay of the collapsed cascade (no memory) ----
    if (tid == 0) {
        const float c = 0.70710678118654752440f;  // 1/sqrt(2) in fp32
        float v0 = c, v1 = 0.0f;                  // H on q=0 applied to |0>
        int key = 0;
        for (int q = 1; q < NBITS; q++) {         // remaining Hadamards
            float s = QUARTER_N * (v0 + v1);      // cross-qubit: s0 == s1
            v0 =  c * s;
            v1 = -c * s;
            key = q;
            if (v0 == 0.0f && v1 == 0.0f) break;  // exact zero at q==2
        }
        if (v0 != 0.0f || v1 != 0.0f) {           // RX layers (zero-skipped)
            for (int k = 0; k < NBITS * 4; k++) {
                int q = k >> 2;
                float d = __cosf(0.5f * theta[k]);
                float s0, s1;
                if (q == key) { s0 = HALF_N * v0;  s1 = HALF_N * v1; }
                else          { float s = QUARTER_N * (v0 + v1); s0 = s; s1 = s; }
                v0 = d * s0;  v1 = d * s1;  key = q;
                if (v0 == 0.0f && v1 == 0.0f) break;
            }
        }
        sh_p0   = v0 * v0;                        // state is real: |amp|^2
        sh_p1   = v1 * v1;
        sh_fast = (v0 == 0.0f) && (v1 == 0.0f);

        // CNOT ladder as GF(2)-linear map: bit_key(sigma(i)) = parity(i & m)
        unsigned L[NBITS];
        for (int b = 0; b < NBITS; b++) L[b] = 1u << b;
        for (int cc = NBITS - 2; cc >= 0; cc--)
            for (int tt = NBITS - 1; tt > cc; tt--)
                L[tt] ^= L[cc];
        sh_mask = L[NBITS - 1];
    }

    // ---- park W2 in shared (stores retire when the loads land) ----
    #pragma unroll
    for (int i = 0; i < 5; i++)
        ((float4*)sh_W2)[tid + 128 * i] = w2r[i];
    __syncthreads();

    const float p0 = sh_p0, p1 = sh_p1;
    float S0 = 0.0f, S1 = 0.0f;

    if (!sh_fast) {
        // Never-taken fallback: probs is two-valued, so
        // probs@W1 = p0*S0 + p1*S1 with S_b[k] = sum over rows i with
        // parity(i & mask)==b of W1[i][k].
        const unsigned m = sh_mask;
        for (unsigned r = 0; r < NSTATES; r++) {
            float w = W1[(size_t)r * 128u + (unsigned)tid];
            if (__popc(r & m) & 1) S1 += w; else S0 += w;
        }
    }

    {   // h = relu(probs @ W1 + b1)  (== relu(b1) on the fast path)
        float z = fmaf(p0, S0, fmaf(p1, S1, b1v));
        h[tid] = z > 0.0f ? z : 0.0f;
    }
    __syncthreads();

    // ---- out = h @ W2 + b2, 4-way split-K over the 128 hidden units ----
    if (tid < 4 * NBITS) {                        // 80 active threads
        const int j = tid % NBITS;                // output column
        const int p = tid / NBITS;                // K-partition (32 each)
        float acc = 0.0f;
        #pragma unroll
        for (int i = 0; i < 32; i++) {
            int k = p * 32 + i;
            acc = fmaf(h[k], sh_W2[k * NBITS + j], acc);
        }
        part[p * NBITS + j] = acc;
    }
    __syncthreads();

    if (tid < NBITS)
        out[tid] = b2v + ((part[tid] + part[NBITS + tid]) +
                          (part[2 * NBITS + tid] + part[3 * NBITS + tid]));
}

extern "C" void kernel_launch(void* const* d_in, const int* in_sizes, int n_in,
                              void* d_out, int out_size) {
    // input order: x [1,4] (unused), theta [20,4], W1 [2^20,128],
    //              b1 [128], W2 [128,20], b2 [20]; output float32 [1,20]
    (void)in_sizes; (void)n_in; (void)out_size;
    const float* theta = (const float*)d_in[1];
    const float* W1    = (const float*)d_in[2];
    const float* b1    = (const float*)d_in[3];
    const float* W2    = (const float*)d_in[4];
    const float* b2    = (const float*)d_in[5];
    qecm_kernel<<<1, 128>>>(theta, W1, b1, W2, b2, (float*)d_out);
}

// round 8
// speedup vs baseline: 1.4048x; 1.4048x over previous
#include <cuda_runtime.h>

#define NBITS     20
#define NSTATES   (1u << NBITS)     // 2^20
#define QUARTER_N 262144.0f         // N/4
#define HALF_N    524288.0f         // N/2

// Single-block, minimal-critical-path kernel.
//
// Math: the reference's buggy diag-gate collapses the state to exactly zero
// at the 3rd Hadamard (fp32-exact: v0' = c*s, v1' = -c*s are exact negatives,
// so the next cross-qubit sum (N/4)(v0+v1) == 0). Hence probs == 0 and
// out = relu(b1) @ W2 + b2. The W1 fallback (probs is two-valued keyed by
// parity(i & mask)) is kept for faithfulness but never executes.
//
// Perf: each thread owns W2 row 'tid' in registers (5x LDG.128, issued in the
// prologue with full MLP, overlapping thread 0's scalar cascade). Epilogue is
// a rank-1 accumulate reduced with a 5-stage warp butterfly shuffle + one
// 4-warp SMEM combine. W2 never touches SMEM; only 2 barriers total.
__global__ void qecm_kernel(const float* __restrict__ theta,  // [20,4]
                            const float* __restrict__ W1,     // [2^20,128]
                            const float* __restrict__ b1,     // [128]
                            const float* __restrict__ W2,     // [128,20]
                            const float* __restrict__ b2,     // [20]
                            float* __restrict__ out) {        // [1,20]
    __shared__ float    warp_part[4][NBITS];      // per-warp reduced vectors
    __shared__ float    sh_p0, sh_p1;
    __shared__ unsigned sh_mask;
    __shared__ int      sh_fast;
    const int tid  = threadIdx.x;
    const int wid  = tid >> 5;
    const int lane = tid & 31;

    // ---- prologue: issue ALL global loads immediately (one round-trip) ----
    float w2row[NBITS];                           // W2[tid][0..19]
    {
        const float4* W2v = (const float4*)W2;    // row tid = float4s [5t,5t+5)
        #pragma unroll
        for (int i = 0; i < 5; i++) {
            float4 v = W2v[tid * 5 + i];
            w2row[4 * i + 0] = v.x; w2row[4 * i + 1] = v.y;
            w2row[4 * i + 2] = v.z; w2row[4 * i + 3] = v.w;
        }
    }
    float b1v = b1[tid];
    float b2v = (tid < NBITS) ? b2[tid] : 0.0f;

    // ---- thread 0: scalar replay of the collapsed cascade (no memory) ----
    if (tid == 0) {
        const float c = 0.70710678118654752440f;  // 1/sqrt(2) in fp32
        float v0 = c, v1 = 0.0f;                  // H on q=0 applied to |0>
        int key = 0;
        for (int q = 1; q < NBITS; q++) {         // remaining Hadamards
            float s = QUARTER_N * (v0 + v1);      // cross-qubit: s0 == s1
            v0 =  c * s;
            v1 = -c * s;
            key = q;
            if (v0 == 0.0f && v1 == 0.0f) break;  // exact zero at q==2
        }
        if (v0 != 0.0f || v1 != 0.0f) {           // RX layers (zero-skipped)
            for (int k = 0; k < NBITS * 4; k++) {
                int q = k >> 2;
                float d = __cosf(0.5f * theta[k]);
                float s0, s1;
                if (q == key) { s0 = HALF_N * v0;  s1 = HALF_N * v1; }
                else          { float s = QUARTER_N * (v0 + v1); s0 = s; s1 = s; }
                v0 = d * s0;  v1 = d * s1;  key = q;
                if (v0 == 0.0f && v1 == 0.0f) break;
            }
        }
        sh_p0   = v0 * v0;                        // state is real: |amp|^2
        sh_p1   = v1 * v1;
        sh_fast = (v0 == 0.0f) && (v1 == 0.0f);

        // CNOT ladder as GF(2)-linear map: bit_key(sigma(i)) = parity(i & m)
        unsigned L[NBITS];
        for (int b = 0; b < NBITS; b++) L[b] = 1u << b;
        for (int cc = NBITS - 2; cc >= 0; cc--)
            for (int tt = NBITS - 1; tt > cc; tt--)
                L[tt] ^= L[cc];
        sh_mask = L[NBITS - 1];
    }
    __syncthreads();                              // barrier #1

    float S0 = 0.0f, S1 = 0.0f;
    if (!sh_fast) {
        // Never-taken fallback: probs@W1 column tid = p0*S0 + p1*S1 with
        // S_b = sum over rows r with parity(r & mask)==b of W1[r][tid].
        const unsigned m = sh_mask;
        for (unsigned r = 0; r < NSTATES; r++) {
            float w = W1[(size_t)r * 128u + (unsigned)tid];
            if (__popc(r & m) & 1) S1 += w; else S0 += w;
        }
    }

    // h_t = relu(probs@W1 + b1)[tid]  (== relu(b1[tid]) on the fast path)
    float z  = fmaf(sh_p0, S0, fmaf(sh_p1, S1, b1v));
    float ht = z > 0.0f ? z : 0.0f;

    // ---- rank-1 epilogue: part[j] = ht * W2[tid][j], butterfly-reduce ----
    float part[NBITS];
    #pragma unroll
    for (int j = 0; j < NBITS; j++) part[j] = ht * w2row[j];

    #pragma unroll
    for (int off = 16; off > 0; off >>= 1) {
        #pragma unroll
        for (int j = 0; j < NBITS; j++)
            part[j] += __shfl_xor_sync(0xffffffffu, part[j], off);
    }
    if (lane == 0) {
        #pragma unroll
        for (int j = 0; j < NBITS; j++) warp_part[wid][j] = part[j];
    }
    __syncthreads();                              // barrier #2

    if (tid < NBITS)
        out[tid] = b2v + ((warp_part[0][tid] + warp_part[1][tid]) +
                          (warp_part[2][tid] + warp_part[3][tid]));
}

extern "C" void kernel_launch(void* const* d_in, const int* in_sizes, int n_in,
                              void* d_out, int out_size) {
    // input order: x [1,4] (unused), theta [20,4], W1 [2^20,128],
    //              b1 [128], W2 [128,20], b2 [20]; output float32 [1,20]
    (void)in_sizes; (void)n_in; (void)out_size;
    const float* theta = (const float*)d_in[1];
    const float* W1    = (const float*)d_in[2];
    const float* b1    = (const float*)d_in[3];
    const float* W2    = (const float*)d_in[4];
    const float* b2    = (const float*)d_in[5];
    qecm_kernel<<<1, 128>>>(theta, W1, b1, W2, b2, (float*)d_out);
}